// round 3
// baseline (speedup 1.0000x reference)
#include <cuda_runtime.h>
#include <cstdint>
#include <math_constants.h>

#define N_NODES   8192
#define NODE_DIM  512
#define HID       256
#define NCLS      16
#define NEDGE     262144
#define MASKW     (N_NODES / 32)   // 256 words per row

// ---------------- scratch (device globals; no allocation allowed) ----------
__device__ uint32_t g_mask[N_NODES * MASKW];   // 8 MB adjacency bitmask
__device__ float    g_h[N_NODES * HID];        // 8 MB  h = x @ W^T
__device__ float    g_f1[N_NODES];
__device__ float    g_f2[N_NODES];
__device__ int      g_is64;

// ---------------- helpers ----------------------------------------------------
__device__ __forceinline__ float warpSum(float v) {
#pragma unroll
    for (int o = 16; o > 0; o >>= 1) v += __shfl_xor_sync(0xffffffffu, v, o);
    return v;
}
__device__ __forceinline__ float warpMax(float v) {
#pragma unroll
    for (int o = 16; o > 0; o >>= 1) v = fmaxf(v, __shfl_xor_sync(0xffffffffu, v, o));
    return v;
}

// packed fp32x2 math (Blackwell sm_103a; 2x fp32 per issue slot)
__device__ __forceinline__ unsigned long long fma2(unsigned long long a,
                                                   unsigned long long b,
                                                   unsigned long long c) {
    unsigned long long d;
    asm("fma.rn.f32x2 %0, %1, %2, %3;" : "=l"(d) : "l"(a), "l"(b), "l"(c));
    return d;
}
__device__ __forceinline__ unsigned long long pack2(float lo, float hi) {
    unsigned long long r;
    asm("mov.b64 %0, {%1, %2};" : "=l"(r) : "f"(lo), "f"(hi));
    return r;
}
__device__ __forceinline__ void unpack2(unsigned long long v, float& lo, float& hi) {
    asm("mov.b64 {%0, %1}, %2;" : "=f"(lo), "=f"(hi) : "l"(v));
}

// ---------------- 1. dtype detect for edge_index ----------------------------
// int64 little-endian with values in [0, 8192): every odd 32-bit word is 0.
// int32: odd words are random node ids -> essentially never all zero.
__global__ void detect_kernel(const uint32_t* __restrict__ e) {
    int is64 = 1;
#pragma unroll
    for (int k = 1; k < 64; k += 2)
        if (e[k] != 0u) is64 = 0;
    g_is64 = is64;
}

// ---------------- 2. zero the bitmask ---------------------------------------
__global__ void zero_mask_kernel() {
    int idx = blockIdx.x * blockDim.x + threadIdx.x;
    int stride = gridDim.x * blockDim.x;
    for (int i = idx; i < N_NODES * MASKW; i += stride) g_mask[i] = 0u;
}

// ---------------- 3. build adjacency bitmask (dedupes automatically) --------
__global__ void build_mask_kernel(const void* __restrict__ edges) {
    int k = blockIdx.x * blockDim.x + threadIdx.x;
    int is64 = g_is64;
    if (k < NEDGE) {
        int r, c;
        if (is64) {
            const long long* p = (const long long*)edges;
            r = (int)p[k];
            c = (int)p[NEDGE + k];
        } else {
            const int* p = (const int*)edges;
            r = p[k];
            c = p[NEDGE + k];
        }
        atomicOr(&g_mask[r * MASKW + (c >> 5)], 1u << (c & 31));
    } else if (k < NEDGE + N_NODES) {
        int i = k - NEDGE;   // self loop
        atomicOr(&g_mask[i * MASKW + (i >> 5)], 1u << (i & 31));
    }
}

// ---------------- 4. h = x @ W^T  (fp32x2 double-buffered GEMM) --------------
// x: [N, 512] row-major, W: [256, 512] row-major, h: [N, 256]
// BM=128, BN=64, BK=16; 256 threads; 8x4 microtile = 4 row-pairs x 4 cols of
// packed f32x2 accumulators. 2-stage SMEM pipeline with register staging.
#define BM 128
#define BN 64
#define BK 16
#define AS_LD 132
#define BS_LD 68

__global__ void __launch_bounds__(256) gemm_kernel(const float* __restrict__ x,
                                                   const float* __restrict__ W) {
    __shared__ float As[2][BK][AS_LD];   // [buf][k][m]
    __shared__ float Bs[2][BK][BS_LD];   // [buf][k][n]

    const int bm = blockIdx.x * BM;
    const int bn = blockIdx.y * BN;
    const int tid = threadIdx.x;
    const int col0 = (tid & 15) * 4;     // 16 col groups
    const int row0 = (tid >> 4) * 8;     // 16 row groups

    const int lrow = tid >> 2;           // 0..63
    const int lkq  = tid & 3;            // 0..3 (k quad)

    unsigned long long acc[4][4];
#pragma unroll
    for (int i = 0; i < 4; i++)
#pragma unroll
        for (int j = 0; j < 4; j++) acc[i][j] = 0ull;

    const float* aptr0 = &x[(size_t)(bm + lrow) * NODE_DIM + lkq * 4];
    const float* aptr1 = &x[(size_t)(bm + lrow + 64) * NODE_DIM + lkq * 4];
    const float* bptr  = &W[(size_t)(bn + lrow) * NODE_DIM + lkq * 4];

    // prologue: stage tile 0
    float4 ra0 = *(const float4*)aptr0;
    float4 ra1 = *(const float4*)aptr1;
    float4 rb  = *(const float4*)bptr;
    {
        float* a = &As[0][lkq * 4][0];
        a[0 * AS_LD + lrow] = ra0.x; a[1 * AS_LD + lrow] = ra0.y;
        a[2 * AS_LD + lrow] = ra0.z; a[3 * AS_LD + lrow] = ra0.w;
        a[0 * AS_LD + lrow + 64] = ra1.x; a[1 * AS_LD + lrow + 64] = ra1.y;
        a[2 * AS_LD + lrow + 64] = ra1.z; a[3 * AS_LD + lrow + 64] = ra1.w;
        float* b = &Bs[0][lkq * 4][0];
        b[0 * BS_LD + lrow] = rb.x; b[1 * BS_LD + lrow] = rb.y;
        b[2 * BS_LD + lrow] = rb.z; b[3 * BS_LD + lrow] = rb.w;
    }
    __syncthreads();

    const int NTILES = NODE_DIM / BK;    // 32
    for (int t = 0; t < NTILES; t++) {
        const int cur = t & 1;
        const int nxt = cur ^ 1;
        const bool have_next = (t + 1) < NTILES;
        if (have_next) {
            int off = (t + 1) * BK;
            ra0 = *(const float4*)(aptr0 + off);
            ra1 = *(const float4*)(aptr1 + off);
            rb  = *(const float4*)(bptr + off);
        }

#pragma unroll
        for (int k = 0; k < BK; k++) {
            const unsigned long long* ap =
                (const unsigned long long*)&As[cur][k][row0];
            unsigned long long a0 = ap[0], a1 = ap[1], a2 = ap[2], a3 = ap[3];
            float4 bv = *(const float4*)&Bs[cur][k][col0];
            unsigned long long b0 = pack2(bv.x, bv.x);
            unsigned long long b1 = pack2(bv.y, bv.y);
            unsigned long long b2 = pack2(bv.z, bv.z);
            unsigned long long b3 = pack2(bv.w, bv.w);

            acc[0][0] = fma2(a0, b0, acc[0][0]);
            acc[0][1] = fma2(a0, b1, acc[0][1]);
            acc[0][2] = fma2(a0, b2, acc[0][2]);
            acc[0][3] = fma2(a0, b3, acc[0][3]);
            acc[1][0] = fma2(a1, b0, acc[1][0]);
            acc[1][1] = fma2(a1, b1, acc[1][1]);
            acc[1][2] = fma2(a1, b2, acc[1][2]);
            acc[1][3] = fma2(a1, b3, acc[1][3]);
            acc[2][0] = fma2(a2, b0, acc[2][0]);
            acc[2][1] = fma2(a2, b1, acc[2][1]);
            acc[2][2] = fma2(a2, b2, acc[2][2]);
            acc[2][3] = fma2(a2, b3, acc[2][3]);
            acc[3][0] = fma2(a3, b0, acc[3][0]);
            acc[3][1] = fma2(a3, b1, acc[3][1]);
            acc[3][2] = fma2(a3, b2, acc[3][2]);
            acc[3][3] = fma2(a3, b3, acc[3][3]);
        }

        if (have_next) {
            float* a = &As[nxt][lkq * 4][0];
            a[0 * AS_LD + lrow] = ra0.x; a[1 * AS_LD + lrow] = ra0.y;
            a[2 * AS_LD + lrow] = ra0.z; a[3 * AS_LD + lrow] = ra0.w;
            a[0 * AS_LD + lrow + 64] = ra1.x; a[1 * AS_LD + lrow + 64] = ra1.y;
            a[2 * AS_LD + lrow + 64] = ra1.z; a[3 * AS_LD + lrow + 64] = ra1.w;
            float* b = &Bs[nxt][lkq * 4][0];
            b[0 * BS_LD + lrow] = rb.x; b[1 * BS_LD + lrow] = rb.y;
            b[2 * BS_LD + lrow] = rb.z; b[3 * BS_LD + lrow] = rb.w;
        }
        __syncthreads();
    }

    // epilogue: unpack row-pairs, store float4 per row
#pragma unroll
    for (int rp = 0; rp < 4; rp++) {
        float lo0, hi0, lo1, hi1, lo2, hi2, lo3, hi3;
        unpack2(acc[rp][0], lo0, hi0);
        unpack2(acc[rp][1], lo1, hi1);
        unpack2(acc[rp][2], lo2, hi2);
        unpack2(acc[rp][3], lo3, hi3);
        int mlo = bm + row0 + rp * 2;
        *(float4*)&g_h[(size_t)mlo * HID + bn + col0] =
            make_float4(lo0, lo1, lo2, lo3);
        *(float4*)&g_h[(size_t)(mlo + 1) * HID + bn + col0] =
            make_float4(hi0, hi1, hi2, hi3);
    }
}

// ---------------- 5. f1 = h@a1, f2 = h@a2 ------------------------------------
__global__ void __launch_bounds__(256) f1f2_kernel(const float* __restrict__ a1,
                                                   const float* __restrict__ a2) {
    int i = blockIdx.x;
    int t = threadIdx.x;
    float v = g_h[(size_t)i * HID + t];
    float s1 = v * a1[t];
    float s2 = v * a2[t];
    s1 = warpSum(s1);
    s2 = warpSum(s2);
    __shared__ float r1[8], r2[8];
    int warp = t >> 5, lane = t & 31;
    if (lane == 0) { r1[warp] = s1; r2[warp] = s2; }
    __syncthreads();
    if (warp == 0) {
        float x1 = (lane < 8) ? r1[lane] : 0.f;
        float x2 = (lane < 8) ? r2[lane] : 0.f;
        x1 = warpSum(x1);
        x2 = warpSum(x2);
        if (lane == 0) { g_f1[i] = x1; g_f2[i] = x2; }
    }
}

// ---------------- 6. fused per-row: softmax + SpMM + ELU + FC ----------------
#define MAXDEG 1024
__global__ void __launch_bounds__(256) gat_kernel(const float* __restrict__ fc_w,
                                                  const float* __restrict__ fc_b,
                                                  float* __restrict__ out) {
    const int i = blockIdx.x;
    const int t = threadIdx.x;
    const int warp = t >> 5, lane = t & 31;

    __shared__ int   nbr[MAXDEG];
    __shared__ float ew[MAXDEG];
    __shared__ float red[8];
    __shared__ float osm[HID];
    __shared__ int   wcnt[8];
    __shared__ int   woff[9];
    __shared__ float s_bcast;

    // ---- deterministic neighbor enumeration via block prefix-sum ----
    uint32_t w = g_mask[i * MASKW + t];
    int pc = __popc(w);
    int incl = pc;
#pragma unroll
    for (int o = 1; o < 32; o <<= 1) {
        int n = __shfl_up_sync(0xffffffffu, incl, o);
        if (lane >= o) incl += n;
    }
    if (lane == 31) wcnt[warp] = incl;
    __syncthreads();
    if (t == 0) {
        int s = 0;
#pragma unroll
        for (int q = 0; q < 8; q++) { woff[q] = s; s += wcnt[q]; }
        woff[8] = s;
    }
    __syncthreads();
    int base = woff[warp] + (incl - pc);
    {
        uint32_t ww = w;
        while (ww && base < MAXDEG) {
            int b = __ffs(ww) - 1;
            ww &= ww - 1;
            nbr[base++] = t * 32 + b;
        }
    }
    __syncthreads();
    const int deg = min(woff[8], MAXDEG);

    // ---- pass 1: leaky-relu scores + row max over nonzero scores ----
    const float f1i = g_f1[i];
    float lmax = -CUDART_INF_F;
    for (int k = t; k < deg; k += 256) {
        int j = nbr[k];
        float s = f1i + g_f2[j];
        s = (s > 0.f) ? s : 0.01f * s;
        ew[k] = s;
        if (s != 0.f) lmax = fmaxf(lmax, s);
    }
    lmax = warpMax(lmax);
    if (lane == 0) red[warp] = lmax;
    __syncthreads();
    if (t == 0) {
        float m = red[0];
#pragma unroll
        for (int q = 1; q < 8; q++) m = fmaxf(m, red[q]);
        s_bcast = m;
    }
    __syncthreads();
    const float mx = s_bcast;
    __syncthreads();

    // ---- pass 2: exp weights + sum (exact-zero scores are masked) ----
    float lsum = 0.f;
    for (int k = t; k < deg; k += 256) {
        float s = ew[k];
        float e = (s == 0.f) ? 0.f : __expf(s - mx);
        ew[k] = e;
        lsum += e;
    }
    lsum = warpSum(lsum);
    if (lane == 0) red[warp] = lsum;
    __syncthreads();
    if (t == 0) {
        float sm = 0.f;
#pragma unroll
        for (int q = 0; q < 8; q++) sm += red[q];
        s_bcast = sm;
    }
    __syncthreads();
    const float inv = 1.f / s_bcast;

    // ---- pass 3: weighted aggregation; thread t owns hidden dim t ----
    float acc = 0.f;
    int k = 0;
    for (; k + 4 <= deg; k += 4) {
        int j0 = nbr[k + 0], j1 = nbr[k + 1], j2 = nbr[k + 2], j3 = nbr[k + 3];
        float e0 = ew[k + 0], e1 = ew[k + 1], e2 = ew[k + 2], e3 = ew[k + 3];
        float h0 = g_h[(size_t)j0 * HID + t];
        float h1 = g_h[(size_t)j1 * HID + t];
        float h2 = g_h[(size_t)j2 * HID + t];
        float h3 = g_h[(size_t)j3 * HID + t];
        acc += e0 * h0 + e1 * h1 + e2 * h2 + e3 * h3;
    }
    for (; k < deg; k++) acc += ew[k] * g_h[(size_t)nbr[k] * HID + t];
    acc *= inv;

    // ELU
    float o = (acc > 0.f) ? acc : expm1f(acc);
    osm[t] = o;
    __syncthreads();

    // tiny FC: 16 classes, 8 warps -> 2 classes per warp
    for (int c = warp; c < NCLS; c += 8) {
        float s = 0.f;
#pragma unroll
        for (int d = lane; d < HID; d += 32) s += osm[d] * fc_w[c * HID + d];
        s = warpSum(s);
        if (lane == 0) out[i * NCLS + c] = s + fc_b[c];
    }
}

// ---------------- launch -----------------------------------------------------
extern "C" void kernel_launch(void* const* d_in, const int* in_sizes, int n_in,
                              void* d_out, int out_size) {
    const float* x    = (const float*)d_in[0];
    const void*  ei   = d_in[1];
    const float* W    = (const float*)d_in[2];
    const float* a1   = (const float*)d_in[3];
    const float* a2   = (const float*)d_in[4];
    const float* fc_w = (const float*)d_in[5];
    const float* fc_b = (const float*)d_in[6];
    float* out = (float*)d_out;

    detect_kernel<<<1, 1>>>((const uint32_t*)ei);
    zero_mask_kernel<<<2048, 256>>>();
    build_mask_kernel<<<(NEDGE + N_NODES + 255) / 256, 256>>>(ei);
    gemm_kernel<<<dim3(N_NODES / BM, HID / BN), 256>>>(x, W);
    f1f2_kernel<<<N_NODES, 256>>>(a1, a2);
    gat_kernel<<<N_NODES, 256>>>(fc_w, fc_b, out);
}